// round 10
// baseline (speedup 1.0000x reference)
#include <cuda_runtime.h>
#include <cuda_bf16.h>
#include <stdint.h>
#include <math.h>

#define T_TOKENS 4096
#define DDIM 768
#define HDIM 2688
#define NEXP 8
#define Z_COEFF 1e-5f

typedef __nv_bfloat16 bf16;

// ===================== helpers =====================
__device__ __forceinline__ uint32_t smem_u32(const void* p) {
    uint32_t a;
    asm("{ .reg .u64 t; cvta.to.shared.u64 t, %1; cvt.u32.u64 %0, t; }" : "=r"(a) : "l"(p));
    return a;
}
__device__ __forceinline__ void ldsm_x4(uint32_t* r, uint32_t a) {
    asm volatile("ldmatrix.sync.aligned.m8n8.x4.shared.b16 {%0,%1,%2,%3}, [%4];"
        : "=r"(r[0]), "=r"(r[1]), "=r"(r[2]), "=r"(r[3]) : "r"(a));
}
__device__ __forceinline__ void mma_bf16(float* c, const uint32_t* a, const uint32_t* b) {
    asm volatile("mma.sync.aligned.m16n8k16.row.col.f32.bf16.bf16.f32 "
        "{%0,%1,%2,%3}, {%4,%5,%6,%7}, {%8,%9}, {%0,%1,%2,%3};"
        : "+f"(c[0]), "+f"(c[1]), "+f"(c[2]), "+f"(c[3])
        : "r"(a[0]), "r"(a[1]), "r"(a[2]), "r"(a[3]), "r"(b[0]), "r"(b[1]));
}
__device__ __forceinline__ void cp16(uint32_t dst, const void* src, uint32_t sz) {
    asm volatile("cp.async.ca.shared.global [%0], [%1], 16, %2;"
        :: "r"(dst), "l"(src), "r"(sz) : "memory");
}
#define CP_COMMIT() asm volatile("cp.async.commit_group;" ::: "memory")
#define CP_WAIT_1() asm volatile("cp.async.wait_group 1;" ::: "memory")
#define CP_WAIT_0() asm volatile("cp.async.wait_group 0;" ::: "memory")

// ===================== device scratch =====================
__device__ int   g_cnt[NEXP];
__device__ int   g_base[NEXP];
__device__ int   g_tok[NEXP][T_TOKENS];
__device__ float g_wt[NEXP][T_TOKENS];
__device__ float g_zsum;
__device__ bf16  g_xh[(size_t)T_TOKENS * DDIM];
__device__ bf16  g_xl[(size_t)T_TOKENS * DDIM];
// transposed split weights: [E][H][D] for gate/up, [E][D][H] for down
__device__ bf16  g_wgh[(size_t)NEXP * HDIM * DDIM];
__device__ bf16  g_wgl[(size_t)NEXP * HDIM * DDIM];
__device__ bf16  g_wuh[(size_t)NEXP * HDIM * DDIM];
__device__ bf16  g_wul[(size_t)NEXP * HDIM * DDIM];
__device__ bf16  g_wdh[(size_t)NEXP * DDIM * HDIM];
__device__ bf16  g_wdl[(size_t)NEXP * DDIM * HDIM];
// split activations, compact rows (g_base[e] + slot)
__device__ bf16  g_acth[(size_t)2 * T_TOKENS * HDIM];
__device__ bf16  g_actl[(size_t)2 * T_TOKENS * HDIM];

// ===================== init (vectorized) =====================
__global__ void k_init(float* __restrict__ out, int n) {
    const int n4 = n >> 2;
    int i = blockIdx.x * blockDim.x + threadIdx.x;
    if (i < n4) ((float4*)out)[i] = make_float4(0.f, 0.f, 0.f, 0.f);
    if (blockIdx.x == 0) {
        if (threadIdx.x < NEXP) g_cnt[threadIdx.x] = 0;
        if (threadIdx.x == 0) {
            g_zsum = 0.0f;
            for (int r = n4 << 2; r < n; r++) out[r] = 0.0f;
        }
    }
}

// ===================== precision split helper =====================
__device__ __forceinline__ void split_bf16(float v, bf16& h, bf16& l) {
    h = __float2bfloat16(v);
    l = __float2bfloat16(v - __bfloat162float(h));
}

// ===================== router (+ fused x hi/lo split) =====================
__global__ void k_router(const float* __restrict__ x,
                         const float* __restrict__ gw,
                         const float* __restrict__ bias) {
    const int t = blockIdx.x;
    __shared__ float s_logits[NEXP];
    const int tid = threadIdx.x;
    const int warp = tid >> 5;
    const int lane = tid & 31;
    const float* xr = x + (size_t)t * DDIM;
    const float* w = gw + (size_t)warp * DDIM;
    float s = 0.0f;
    for (int d = lane; d < DDIM; d += 32) s = fmaf(xr[d], w[d], s);
    #pragma unroll
    for (int o = 16; o; o >>= 1) s += __shfl_xor_sync(0xffffffffu, s, o);
    if (lane == 0) s_logits[warp] = s;

    // fused x split: this block owns token t's row (L1-hot)
    #pragma unroll
    for (int i = tid; i < DDIM; i += 256) {
        bf16 h, l; split_bf16(xr[i], h, l);
        g_xh[(size_t)t * DDIM + i] = h;
        g_xl[(size_t)t * DDIM + i] = l;
    }

    __syncthreads();
    if (tid == 0) {
        float l[NEXP];
        #pragma unroll
        for (int e = 0; e < NEXP; e++) l[e] = s_logits[e];
        int i0 = 0, i1 = -1;
        float b0 = -1e30f, b1 = -1e30f;
        #pragma unroll
        for (int e = 0; e < NEXP; e++) {
            float v = l[e] + bias[e];
            if (v > b0) { b1 = b0; i1 = i0; b0 = v; i0 = e; }
            else if (v > b1) { b1 = v; i1 = e; }
        }
        float l0 = l[i0], l1 = l[i1];
        float m = fmaxf(l0, l1);
        float e0 = expf(l0 - m), e1 = expf(l1 - m);
        float inv = 1.0f / (e0 + e1);
        float mx = l[0];
        #pragma unroll
        for (int e = 1; e < NEXP; e++) mx = fmaxf(mx, l[e]);
        float se = 0.0f;
        #pragma unroll
        for (int e = 0; e < NEXP; e++) se += expf(l[e] - mx);
        float lse = mx + logf(se);
        atomicAdd(&g_zsum, lse * lse);
        int p0 = atomicAdd(&g_cnt[i0], 1);
        g_tok[i0][p0] = t; g_wt[i0][p0] = e0 * inv;
        int p1 = atomicAdd(&g_cnt[i1], 1);
        g_tok[i1][p1] = t; g_wt[i1][p1] = e1 * inv;
    }
}

__global__ void k_offsets() {
    if (threadIdx.x == 0) {
        int s = 0;
        for (int e = 0; e < NEXP; e++) { g_base[e] = s; s += g_cnt[e]; }
    }
}

// transpose+split w_gate / w_up : [E][D][H] -> [E][H][D], vectorized 16B stores
__global__ __launch_bounds__(256) void k_split_wgu(const float* __restrict__ w_gate,
                                                   const float* __restrict__ w_up) {
    __shared__ float t[64][33];
    const int z = blockIdx.z;
    const int e = z >> 1;
    const bool up = z & 1;
    const float* src = (up ? w_up : w_gate) + (size_t)e * DDIM * HDIM;
    bf16* oh = (up ? g_wuh : g_wgh) + (size_t)e * HDIM * DDIM;
    bf16* ol = (up ? g_wul : g_wgl) + (size_t)e * HDIM * DDIM;
    const int h0 = blockIdx.x * 32, d0 = blockIdx.y * 64;
    const int c = threadIdx.x & 31, r0 = threadIdx.x >> 5;
    #pragma unroll
    for (int i = 0; i < 64; i += 8)
        t[r0 + i][c] = src[(size_t)(d0 + r0 + i) * HDIM + h0 + c];
    __syncthreads();
    const int h = threadIdx.x >> 3, dg = threadIdx.x & 7;
    union { bf16 b[8]; uint4 u; } H, L;
    #pragma unroll
    for (int j = 0; j < 8; j++) split_bf16(t[dg * 8 + j][h], H.b[j], L.b[j]);
    const size_t o = (size_t)(h0 + h) * DDIM + d0 + dg * 8;
    *(uint4*)(oh + o) = H.u;
    *(uint4*)(ol + o) = L.u;
}

// transpose+split w_down : [E][H][D] -> [E][D][H], vectorized 16B stores
__global__ __launch_bounds__(256) void k_split_wdn(const float* __restrict__ w_down) {
    __shared__ float t[64][33];
    const int e = blockIdx.z;
    const float* src = w_down + (size_t)e * HDIM * DDIM;
    bf16* oh = g_wdh + (size_t)e * DDIM * HDIM;
    bf16* ol = g_wdl + (size_t)e * DDIM * HDIM;
    const int d0 = blockIdx.x * 32, h0 = blockIdx.y * 64;
    const int c = threadIdx.x & 31, r0 = threadIdx.x >> 5;
    #pragma unroll
    for (int i = 0; i < 64; i += 8)
        t[r0 + i][c] = src[(size_t)(h0 + r0 + i) * DDIM + d0 + c];
    __syncthreads();
    const int d = threadIdx.x >> 3, hg = threadIdx.x & 7;
    union { bf16 b[8]; uint4 u; } H, L;
    #pragma unroll
    for (int j = 0; j < 8; j++) split_bf16(t[hg * 8 + j][d], H.b[j], L.b[j]);
    const size_t o = (size_t)(d0 + d) * HDIM + h0 + hg * 8;
    *(uint4*)(oh + o) = H.u;
    *(uint4*)(ol + o) = L.u;
}

// ===================== GEMM tiling constants =====================
#define PITCH 80                      // A tiles: 64B data + 16B pad; conflict-free ldmatrix
#define A_TILE (128 * PITCH)          // 10240 B (128 rows x 32 k)
// B tiles: unpadded 64B rows with XOR swizzle (seg ^= row&3); 2-way ldsm conflict, smaller stage
#define B1_TILE (64 * 64)             // 4096 B (phase1: 64 N-rows)
#define B2_TILE (128 * 64)            // 8192 B (phase2: 128 N-rows)
#define STG1 (2 * A_TILE + 4 * B1_TILE)  // 36864
#define STG2 (2 * A_TILE + 2 * B2_TILE)  // 36864
#define NCH1 (DDIM / 32)              // 24
#define NCH2 (HDIM / 32)              // 84
#define NSTAGE 3

__device__ __forceinline__ uint32_t bswz(int row, int seg) {
    return (uint32_t)(row * 64 + ((seg ^ (row & 3)) << 4));
}

// ===================== phase 1: gate+up GEMM (HMMA split-3) =====================
// 256 threads, M=128 N=64 K=32, warps 2m x 4n, 3-stage cp.async, 1 sync/chunk
__global__ __launch_bounds__(256, 2)
void k_gu_mma() {
    const int e = blockIdx.z;
    const int cnt = g_cnt[e];
    const int m0 = blockIdx.y * 128;
    if (m0 >= cnt) return;
    const int n0 = blockIdx.x * 64;

    extern __shared__ char sm[];
    __shared__ int s_tok[128];
    const int tid = threadIdx.x, lane = tid & 31, wid = tid >> 5;
    const int wm = wid >> 2, wn = wid & 3;
    if (tid < 128) { int s = m0 + tid; s_tok[tid] = (s < cnt) ? g_tok[e][s] : -1; }
    __syncthreads();
    const uint32_t smb = smem_u32(sm);

    const size_t woff = (size_t)(e * HDIM + n0) * DDIM;
    const bf16* wb0 = g_wgh + woff;
    const bf16* wb1 = g_wgl + woff;
    const bf16* wb2 = g_wuh + woff;
    const bf16* wb3 = g_wul + woff;

    auto issue = [&](int stage, int d0) {
        uint32_t sb = smb + stage * STG1;
        #pragma unroll
        for (int i = 0; i < 4; i++) {       // A: xh, xl (1024 cps)
            int idx = tid + i * 256;
            int tile = idx >> 9, rem = idx & 511, row = rem >> 2, seg = rem & 3;
            int tok = s_tok[row];
            const bf16* src = (tile ? g_xl : g_xh)
                + (size_t)(tok < 0 ? 0 : tok) * DDIM + d0 + seg * 8;
            cp16(sb + tile * A_TILE + row * PITCH + seg * 16, src, tok >= 0 ? 16u : 0u);
        }
        #pragma unroll
        for (int i = 0; i < 4; i++) {       // B: 4 matrices x 64 rows x 4 segs
            int idx = tid + i * 256;
            int mat = idx >> 8, rem = idx & 255, row = rem >> 2, seg = rem & 3;
            const bf16* src = (mat == 0 ? wb0 : mat == 1 ? wb1 : mat == 2 ? wb2 : wb3)
                + (size_t)row * DDIM + d0 + seg * 8;
            cp16(sb + 2 * A_TILE + mat * B1_TILE + bswz(row, seg), src, 16u);
        }
        CP_COMMIT();
    };

    float accg[4][2][4] = {};
    float accu[4][2][4] = {};

    issue(0, 0);
    issue(1, 32);
    const uint32_t aBase = (uint32_t)((wm * 64 + (lane & 15)) * PITCH + ((lane >> 4) * 16));
    const int brow = wn * 16 + (lane & 7) + ((lane & 16) ? 8 : 0);
    const int bseg0 = (lane >> 3) & 1;

    int stage = 0;
    for (int c = 0; c < NCH1; c++) {
        if (c + 1 < NCH1) CP_WAIT_1(); else CP_WAIT_0();
        __syncthreads();
        if (c + 2 < NCH1) {
            int ns = stage + 2; if (ns >= NSTAGE) ns -= NSTAGE;
            issue(ns, (c + 2) * 32);
        }
        const uint32_t sA = smb + stage * STG1;
        const uint32_t sB = sA + 2 * A_TILE;
        #pragma unroll
        for (int ks = 0; ks < 2; ks++) {
            const uint32_t kc = ks * 32;
            const uint32_t bo = bswz(brow, bseg0 + 2 * ks);
            uint32_t b0[4], b1[4], b2[4], b3[4];
            ldsm_x4(b0, sB + 0 * B1_TILE + bo);
            ldsm_x4(b1, sB + 1 * B1_TILE + bo);
            ldsm_x4(b2, sB + 2 * B1_TILE + bo);
            ldsm_x4(b3, sB + 3 * B1_TILE + bo);
            #pragma unroll
            for (int mt = 0; mt < 4; mt++) {
                uint32_t ah[4], al[4];
                const uint32_t ao = aBase + mt * 16 * PITCH + kc;
                ldsm_x4(ah, sA + ao);
                ldsm_x4(al, sA + A_TILE + ao);
                mma_bf16(accg[mt][0], ah, b0 + 0); mma_bf16(accg[mt][1], ah, b0 + 2);
                mma_bf16(accg[mt][0], ah, b1 + 0); mma_bf16(accg[mt][1], ah, b1 + 2);
                mma_bf16(accg[mt][0], al, b0 + 0); mma_bf16(accg[mt][1], al, b0 + 2);
                mma_bf16(accu[mt][0], ah, b2 + 0); mma_bf16(accu[mt][1], ah, b2 + 2);
                mma_bf16(accu[mt][0], ah, b3 + 0); mma_bf16(accu[mt][1], ah, b3 + 2);
                mma_bf16(accu[mt][0], al, b2 + 0); mma_bf16(accu[mt][1], al, b2 + 2);
            }
        }
        stage++; if (stage >= NSTAGE) stage = 0;
    }

    // epilogue: act = silu(g) * u, split to bf16 hi/lo
    const int rw = lane >> 2;
    const int cw = (lane & 3) * 2;
    #pragma unroll
    for (int mt = 0; mt < 4; mt++) {
        #pragma unroll
        for (int half = 0; half < 2; half++) {
            const int slot = m0 + wm * 64 + mt * 16 + rw + half * 8;
            if (slot < cnt) {
                const size_t rowoff = (size_t)(g_base[e] + slot) * HDIM;
                #pragma unroll
                for (int nt = 0; nt < 2; nt++) {
                    float g0 = accg[mt][nt][half * 2 + 0], g1 = accg[mt][nt][half * 2 + 1];
                    float u0 = accu[mt][nt][half * 2 + 0], u1 = accu[mt][nt][half * 2 + 1];
                    float v0 = (g0 / (1.0f + __expf(-g0))) * u0;
                    float v1 = (g1 / (1.0f + __expf(-g1))) * u1;
                    const int col = n0 + wn * 16 + nt * 8 + cw;
                    bf16 h0, l0, h1, l1;
                    split_bf16(v0, h0, l0);
                    split_bf16(v1, h1, l1);
                    __nv_bfloat162 ph; ph.x = h0; ph.y = h1;
                    __nv_bfloat162 pl; pl.x = l0; pl.y = l1;
                    *(__nv_bfloat162*)(g_acth + rowoff + col) = ph;
                    *(__nv_bfloat162*)(g_actl + rowoff + col) = pl;
                }
            }
        }
    }
}

// ===================== phase 2: down GEMM + weighted scatter =====================
// 256 threads, M=128 N=128 (over D) K=32, warps 2m x 4n (warp N=32), 3-stage
__global__ __launch_bounds__(256, 2)
void k_down_mma(float* __restrict__ out) {
    const int e = blockIdx.z;
    const int cnt = g_cnt[e];
    const int m0 = blockIdx.y * 128;
    if (m0 >= cnt) return;
    const int n0 = blockIdx.x * 128;   // over D: 6 tiles

    extern __shared__ char sm[];
    __shared__ int   s_tok[128];
    __shared__ float s_wt[128];
    const int tid = threadIdx.x, lane = tid & 31, wid = tid >> 5;
    const int wm = wid >> 2, wn = wid & 3;
    if (tid < 128) {
        int s = m0 + tid;
        s_tok[tid] = (s < cnt) ? g_tok[e][s] : -1;
        s_wt[tid]  = (s < cnt) ? g_wt[e][s] : 0.0f;
    }
    __syncthreads();
    const uint32_t smb = smem_u32(sm);

    const size_t woff = (size_t)(e * DDIM + n0) * HDIM;
    const bf16* wb0 = g_wdh + woff;
    const bf16* wb1 = g_wdl + woff;
    const size_t abase = (size_t)(g_base[e] + m0) * HDIM;

    auto issue = [&](int stage, int h0) {
        uint32_t sb = smb + stage * STG2;
        #pragma unroll
        for (int i = 0; i < 4; i++) {       // A: acth, actl (128 rows x 32k each)
            int idx = tid + i * 256;
            int tile = idx >> 9, rem = idx & 511, row = rem >> 2, seg = rem & 3;
            const bool ok = (m0 + row) < cnt;
            const bf16* src = (tile ? g_actl : g_acth)
                + abase + (size_t)(ok ? row : 0) * HDIM + h0 + seg * 8;
            cp16(sb + tile * A_TILE + row * PITCH + seg * 16, src, ok ? 16u : 0u);
        }
        #pragma unroll
        for (int i = 0; i < 4; i++) {       // B: wdh, wdl (128 N-rows x 4 segs each)
            int idx = tid + i * 256;
            int mat = idx >> 9, rem = idx & 511, row = rem >> 2, seg = rem & 3;
            const bf16* src = (mat == 0 ? wb0 : wb1) + (size_t)row * HDIM + h0 + seg * 8;
            cp16(sb + 2 * A_TILE + mat * B2_TILE + bswz(row, seg), src, 16u);
        }
        CP_COMMIT();
    };

    float acc[4][4][4] = {};

    issue(0, 0);
    issue(1, 32);
    const uint32_t aBase = (uint32_t)((wm * 64 + (lane & 15)) * PITCH + ((lane >> 4) * 16));
    const int brow = wn * 32 + (lane & 7) + ((lane & 16) ? 8 : 0);
    const int bseg0 = (lane >> 3) & 1;

    int stage = 0;
    for (int c = 0; c < NCH2; c++) {
        if (c + 1 < NCH2) CP_WAIT_1(); else CP_WAIT_0();
        __syncthreads();
        if (c + 2 < NCH2) {
            int ns = stage + 2; if (ns >= NSTAGE) ns -= NSTAGE;
            issue(ns, (c + 2) * 32);
        }
        const uint32_t sA = smb + stage * STG2;
        const uint32_t sB = sA + 2 * A_TILE;
        #pragma unroll
        for (int ks = 0; ks < 2; ks++) {
            const uint32_t kc = ks * 32;
            const uint32_t bo = bswz(brow, bseg0 + 2 * ks);
            uint32_t bh[2][4], bl[2][4];
            ldsm_x4(bh[0], sB + 0 * B2_TILE + bo);
            ldsm_x4(bh[1], sB + 0 * B2_TILE + bo + 16 * 64);
            ldsm_x4(bl[0], sB + 1 * B2_TILE + bo);
            ldsm_x4(bl[1], sB + 1 * B2_TILE + bo + 16 * 64);
            #pragma unroll
            for (int mt = 0; mt < 4; mt++) {
                uint32_t ah[4], al[4];
                const uint32_t ao = aBase + mt * 16 * PITCH + kc;
                ldsm_x4(ah, sA + ao);
                ldsm_x4(al, sA + A_TILE + ao);
                #pragma unroll
                for (int ns = 0; ns < 2; ns++) {
                    mma_bf16(acc[mt][ns * 2 + 0], ah, bh[ns] + 0);
                    mma_bf16(acc[mt][ns * 2 + 1], ah, bh[ns] + 2);
                    mma_bf16(acc[mt][ns * 2 + 0], ah, bl[ns] + 0);
                    mma_bf16(acc[mt][ns * 2 + 1], ah, bl[ns] + 2);
                    mma_bf16(acc[mt][ns * 2 + 0], al, bh[ns] + 0);
                    mma_bf16(acc[mt][ns * 2 + 1], al, bh[ns] + 2);
                }
            }
        }
        stage++; if (stage >= NSTAGE) stage = 0;
    }

    // epilogue: out[token] += weight * val (atomic)
    const int rw = lane >> 2;
    const int cw = (lane & 3) * 2;
    #pragma unroll
    for (int mt = 0; mt < 4; mt++) {
        #pragma unroll
        for (int half = 0; half < 2; half++) {
            const int lrow = wm * 64 + mt * 16 + rw + half * 8;
            const int slot = m0 + lrow;
            if (slot < cnt) {
                const int t = s_tok[lrow];
                const float w = s_wt[lrow];
                float* dst = out + (size_t)t * DDIM;
                #pragma unroll
                for (int nt = 0; nt < 4; nt++) {
                    const int col = n0 + wn * 32 + nt * 8 + cw;
                    atomicAdd(dst + col,     w * acc[mt][nt][half * 2 + 0]);
                    atomicAdd(dst + col + 1, w * acc[mt][nt][half * 2 + 1]);
                }
            }
        }
    }
}

// ===================== z-loss =====================
__global__ void k_zloss(float* __restrict__ zout) {
    zout[0] = Z_COEFF * g_zsum / (float)T_TOKENS;
}

// ===================== launch =====================
extern "C" void kernel_launch(void* const* d_in, const int* in_sizes, int n_in,
                              void* d_out, int out_size) {
    const float* x           = (const float*)d_in[0];
    const float* gate_w      = (const float*)d_in[1];
    const float* expert_bias = (const float*)d_in[2];
    const float* w_gate      = (const float*)d_in[3];
    const float* w_up        = (const float*)d_in[4];
    const float* w_down      = (const float*)d_in[5];
    float* out = (float*)d_out;

    cudaFuncSetAttribute(k_gu_mma,   cudaFuncAttributeMaxDynamicSharedMemorySize, NSTAGE * STG1);
    cudaFuncSetAttribute(k_down_mma, cudaFuncAttributeMaxDynamicSharedMemorySize, NSTAGE * STG2);

    const int n_main = T_TOKENS * DDIM;

    k_init<<<(out_size / 4 + 255) / 256, 256>>>(out, out_size);
    k_router<<<T_TOKENS, 256>>>(x, gate_w, expert_bias);
    k_offsets<<<1, 32>>>();
    k_split_wgu<<<dim3(HDIM / 32, DDIM / 64, NEXP * 2), 256>>>(w_gate, w_up);
    k_split_wdn<<<dim3(DDIM / 32, HDIM / 64, NEXP), 256>>>(w_down);
    k_gu_mma<<<dim3(HDIM / 64, T_TOKENS / 128, NEXP), 256, NSTAGE * STG1>>>();
    k_down_mma<<<dim3(DDIM / 128, T_TOKENS / 128, NEXP), 256, NSTAGE * STG2>>>(out);
    if (out_size > n_main) k_zloss<<<1, 1>>>(out + n_main);
}

// round 11
// speedup vs baseline: 1.1889x; 1.1889x over previous
#include <cuda_runtime.h>
#include <cuda_bf16.h>
#include <stdint.h>
#include <math.h>

#define T_TOKENS 4096
#define DDIM 768
#define HDIM 2688
#define NEXP 8
#define Z_COEFF 1e-5f

typedef __nv_bfloat16 bf16;

// ===================== helpers =====================
__device__ __forceinline__ uint32_t smem_u32(const void* p) {
    uint32_t a;
    asm("{ .reg .u64 t; cvta.to.shared.u64 t, %1; cvt.u32.u64 %0, t; }" : "=r"(a) : "l"(p));
    return a;
}
__device__ __forceinline__ void ldsm_x4(uint32_t* r, uint32_t a) {
    asm volatile("ldmatrix.sync.aligned.m8n8.x4.shared.b16 {%0,%1,%2,%3}, [%4];"
        : "=r"(r[0]), "=r"(r[1]), "=r"(r[2]), "=r"(r[3]) : "r"(a));
}
__device__ __forceinline__ void mma_bf16(float* c, const uint32_t* a, const uint32_t* b) {
    asm volatile("mma.sync.aligned.m16n8k16.row.col.f32.bf16.bf16.f32 "
        "{%0,%1,%2,%3}, {%4,%5,%6,%7}, {%8,%9}, {%0,%1,%2,%3};"
        : "+f"(c[0]), "+f"(c[1]), "+f"(c[2]), "+f"(c[3])
        : "r"(a[0]), "r"(a[1]), "r"(a[2]), "r"(a[3]), "r"(b[0]), "r"(b[1]));
}
__device__ __forceinline__ void cp16(uint32_t dst, const void* src, uint32_t sz) {
    asm volatile("cp.async.ca.shared.global [%0], [%1], 16, %2;"
        :: "r"(dst), "l"(src), "r"(sz) : "memory");
}
#define CP_COMMIT() asm volatile("cp.async.commit_group;" ::: "memory")
#define CP_WAIT_1() asm volatile("cp.async.wait_group 1;" ::: "memory")
#define CP_WAIT_0() asm volatile("cp.async.wait_group 0;" ::: "memory")

// ===================== device scratch =====================
__device__ int   g_cnt[NEXP];
__device__ int   g_base[NEXP];
__device__ int   g_tok[NEXP][T_TOKENS];
__device__ float g_wt[NEXP][T_TOKENS];
__device__ float g_zsum;
__device__ bf16  g_xh[(size_t)T_TOKENS * DDIM];
__device__ bf16  g_xl[(size_t)T_TOKENS * DDIM];
// transposed split weights: [E][H][D] for gate/up, [E][D][H] for down
__device__ bf16  g_wgh[(size_t)NEXP * HDIM * DDIM];
__device__ bf16  g_wgl[(size_t)NEXP * HDIM * DDIM];
__device__ bf16  g_wuh[(size_t)NEXP * HDIM * DDIM];
__device__ bf16  g_wul[(size_t)NEXP * HDIM * DDIM];
__device__ bf16  g_wdh[(size_t)NEXP * DDIM * HDIM];
__device__ bf16  g_wdl[(size_t)NEXP * DDIM * HDIM];
// split activations, compact rows (g_base[e] + slot)
__device__ bf16  g_acth[(size_t)2 * T_TOKENS * HDIM];
__device__ bf16  g_actl[(size_t)2 * T_TOKENS * HDIM];

// ===================== init (vectorized) =====================
__global__ void k_init(float* __restrict__ out, int n) {
    const int n4 = n >> 2;
    int i = blockIdx.x * blockDim.x + threadIdx.x;
    if (i < n4) ((float4*)out)[i] = make_float4(0.f, 0.f, 0.f, 0.f);
    if (blockIdx.x == 0) {
        if (threadIdx.x < NEXP) g_cnt[threadIdx.x] = 0;
        if (threadIdx.x == 0) {
            g_zsum = 0.0f;
            for (int r = n4 << 2; r < n; r++) out[r] = 0.0f;
        }
    }
}

// ===================== precision split helper =====================
__device__ __forceinline__ void split_bf16(float v, bf16& h, bf16& l) {
    h = __float2bfloat16(v);
    l = __float2bfloat16(v - __bfloat162float(h));
}

// ===================== router (+ fused x hi/lo split) =====================
__global__ void k_router(const float* __restrict__ x,
                         const float* __restrict__ gw,
                         const float* __restrict__ bias) {
    const int t = blockIdx.x;
    __shared__ float s_logits[NEXP];
    const int tid = threadIdx.x;
    const int warp = tid >> 5;
    const int lane = tid & 31;
    const float* xr = x + (size_t)t * DDIM;
    const float* w = gw + (size_t)warp * DDIM;
    float s = 0.0f;
    for (int d = lane; d < DDIM; d += 32) s = fmaf(xr[d], w[d], s);
    #pragma unroll
    for (int o = 16; o; o >>= 1) s += __shfl_xor_sync(0xffffffffu, s, o);
    if (lane == 0) s_logits[warp] = s;

    // fused x split: this block owns token t's row (L1-hot)
    for (int i = tid; i < DDIM; i += 256) {
        bf16 h, l; split_bf16(xr[i], h, l);
        g_xh[(size_t)t * DDIM + i] = h;
        g_xl[(size_t)t * DDIM + i] = l;
    }

    __syncthreads();
    if (tid == 0) {
        float l[NEXP];
        #pragma unroll
        for (int e = 0; e < NEXP; e++) l[e] = s_logits[e];
        int i0 = 0, i1 = -1;
        float b0 = -1e30f, b1 = -1e30f;
        #pragma unroll
        for (int e = 0; e < NEXP; e++) {
            float v = l[e] + bias[e];
            if (v > b0) { b1 = b0; i1 = i0; b0 = v; i0 = e; }
            else if (v > b1) { b1 = v; i1 = e; }
        }
        float l0 = l[i0], l1 = l[i1];
        float m = fmaxf(l0, l1);
        float e0 = expf(l0 - m), e1 = expf(l1 - m);
        float inv = 1.0f / (e0 + e1);
        float mx = l[0];
        #pragma unroll
        for (int e = 1; e < NEXP; e++) mx = fmaxf(mx, l[e]);
        float se = 0.0f;
        #pragma unroll
        for (int e = 0; e < NEXP; e++) se += expf(l[e] - mx);
        float lse = mx + logf(se);
        atomicAdd(&g_zsum, lse * lse);
        int p0 = atomicAdd(&g_cnt[i0], 1);
        g_tok[i0][p0] = t; g_wt[i0][p0] = e0 * inv;
        int p1 = atomicAdd(&g_cnt[i1], 1);
        g_tok[i1][p1] = t; g_wt[i1][p1] = e1 * inv;
    }
}

__global__ void k_offsets() {
    if (threadIdx.x == 0) {
        int s = 0;
        for (int e = 0; e < NEXP; e++) { g_base[e] = s; s += g_cnt[e]; }
    }
}

// transpose+split w_gate / w_up : [E][D][H] -> [E][H][D], vectorized 16B stores
__global__ __launch_bounds__(256) void k_split_wgu(const float* __restrict__ w_gate,
                                                   const float* __restrict__ w_up) {
    __shared__ float t[64][33];
    const int z = blockIdx.z;
    const int e = z >> 1;
    const bool up = z & 1;
    const float* src = (up ? w_up : w_gate) + (size_t)e * DDIM * HDIM;
    bf16* oh = (up ? g_wuh : g_wgh) + (size_t)e * HDIM * DDIM;
    bf16* ol = (up ? g_wul : g_wgl) + (size_t)e * HDIM * DDIM;
    const int h0 = blockIdx.x * 32, d0 = blockIdx.y * 64;
    const int c = threadIdx.x & 31, r0 = threadIdx.x >> 5;
    #pragma unroll
    for (int i = 0; i < 64; i += 8)
        t[r0 + i][c] = src[(size_t)(d0 + r0 + i) * HDIM + h0 + c];
    __syncthreads();
    const int h = threadIdx.x >> 3, dg = threadIdx.x & 7;
    union { bf16 b[8]; uint4 u; } H, L;
    #pragma unroll
    for (int j = 0; j < 8; j++) split_bf16(t[dg * 8 + j][h], H.b[j], L.b[j]);
    const size_t o = (size_t)(h0 + h) * DDIM + d0 + dg * 8;
    *(uint4*)(oh + o) = H.u;
    *(uint4*)(ol + o) = L.u;
}

// transpose+split w_down : [E][H][D] -> [E][D][H], vectorized 16B stores
__global__ __launch_bounds__(256) void k_split_wdn(const float* __restrict__ w_down) {
    __shared__ float t[64][33];
    const int e = blockIdx.z;
    const float* src = w_down + (size_t)e * HDIM * DDIM;
    bf16* oh = g_wdh + (size_t)e * DDIM * HDIM;
    bf16* ol = g_wdl + (size_t)e * DDIM * HDIM;
    const int d0 = blockIdx.x * 32, h0 = blockIdx.y * 64;
    const int c = threadIdx.x & 31, r0 = threadIdx.x >> 5;
    #pragma unroll
    for (int i = 0; i < 64; i += 8)
        t[r0 + i][c] = src[(size_t)(h0 + r0 + i) * DDIM + d0 + c];
    __syncthreads();
    const int d = threadIdx.x >> 3, hg = threadIdx.x & 7;
    union { bf16 b[8]; uint4 u; } H, L;
    #pragma unroll
    for (int j = 0; j < 8; j++) split_bf16(t[hg * 8 + j][d], H.b[j], L.b[j]);
    const size_t o = (size_t)(d0 + d) * HDIM + h0 + hg * 8;
    *(uint4*)(oh + o) = H.u;
    *(uint4*)(ol + o) = L.u;
}

// ===================== GEMM tiling constants (R9-proven) =====================
#define PITCH 80                      // 64B data + 16B pad; conflict-free ldmatrix
#define A_TILE (128 * PITCH)          // 10240 B (128 rows x 32 k)
#define B_TILE (64 * PITCH)           // 5120 B
#define STG1 (2 * A_TILE + 4 * B_TILE)   // 40960
#define STG2 (4 * A_TILE)                // 40960 (A hi/lo + B 128-row hi/lo)
#define NCH1 (DDIM / 32)              // 24
#define NCH2 (HDIM / 32)              // 84

// ===================== phase 1: gate+up GEMM (R9-proven config) =====================
// 256 threads, M=128 N=64 K=32, warps 2m x 4n, 2-stage cp.async
__global__ __launch_bounds__(256, 2)
void k_gu_mma() {
    const int e = blockIdx.z;
    const int cnt = g_cnt[e];
    const int m0 = blockIdx.y * 128;
    if (m0 >= cnt) return;
    const int n0 = blockIdx.x * 64;

    extern __shared__ char sm[];
    __shared__ int s_tok[128];
    const int tid = threadIdx.x, lane = tid & 31, wid = tid >> 5;
    const int wm = wid >> 2, wn = wid & 3;
    if (tid < 128) { int s = m0 + tid; s_tok[tid] = (s < cnt) ? g_tok[e][s] : -1; }
    __syncthreads();
    const uint32_t smb = smem_u32(sm);

    const size_t woff = (size_t)(e * HDIM + n0) * DDIM;
    const bf16* wb0 = g_wgh + woff;
    const bf16* wb1 = g_wgl + woff;
    const bf16* wb2 = g_wuh + woff;
    const bf16* wb3 = g_wul + woff;

    auto issue = [&](int stage, int d0) {
        uint32_t sb = smb + stage * STG1;
        #pragma unroll
        for (int i = 0; i < 4; i++) {
            int idx = tid + i * 256;
            int tile = idx >> 9, rem = idx & 511, row = rem >> 2, seg = rem & 3;
            int tok = s_tok[row];
            const bf16* src = (tile ? g_xl : g_xh)
                + (size_t)(tok < 0 ? 0 : tok) * DDIM + d0 + seg * 8;
            cp16(sb + tile * A_TILE + row * PITCH + seg * 16, src, tok >= 0 ? 16u : 0u);
        }
        #pragma unroll
        for (int i = 0; i < 4; i++) {
            int idx = tid + i * 256;
            int mat = idx >> 8, rem = idx & 255, row = rem >> 2, seg = rem & 3;
            const bf16* src = (mat == 0 ? wb0 : mat == 1 ? wb1 : mat == 2 ? wb2 : wb3)
                + (size_t)row * DDIM + d0 + seg * 8;
            cp16(sb + 2 * A_TILE + mat * B_TILE + row * PITCH + seg * 16, src, 16u);
        }
        CP_COMMIT();
    };

    float accg[4][2][4] = {};
    float accu[4][2][4] = {};

    issue(0, 0);
    const uint32_t aBase = (uint32_t)((wm * 64 + (lane & 15)) * PITCH + ((lane >> 4) * 16));
    const uint32_t bBase = (uint32_t)((wn * 16 + (lane & 7) + ((lane & 16) ? 8 : 0)) * PITCH
                                      + (((lane >> 3) & 1) * 16));

    for (int c = 0; c < NCH1; c++) {
        if (c + 1 < NCH1) { issue((c + 1) & 1, (c + 1) * 32); CP_WAIT_1(); }
        else               { CP_WAIT_0(); }
        __syncthreads();
        const uint32_t sA = smb + (c & 1) * STG1;
        const uint32_t sB = sA + 2 * A_TILE;
        #pragma unroll
        for (int ks = 0; ks < 2; ks++) {
            const uint32_t kc = ks * 32;
            uint32_t b0[4], b1[4], b2[4], b3[4];
            ldsm_x4(b0, sB + 0 * B_TILE + bBase + kc);
            ldsm_x4(b1, sB + 1 * B_TILE + bBase + kc);
            ldsm_x4(b2, sB + 2 * B_TILE + bBase + kc);
            ldsm_x4(b3, sB + 3 * B_TILE + bBase + kc);
            #pragma unroll
            for (int mt = 0; mt < 4; mt++) {
                uint32_t ah[4], al[4];
                const uint32_t ao = aBase + mt * 16 * PITCH + kc;
                ldsm_x4(ah, sA + ao);
                ldsm_x4(al, sA + A_TILE + ao);
                mma_bf16(accg[mt][0], ah, b0 + 0); mma_bf16(accg[mt][1], ah, b0 + 2);
                mma_bf16(accg[mt][0], ah, b1 + 0); mma_bf16(accg[mt][1], ah, b1 + 2);
                mma_bf16(accg[mt][0], al, b0 + 0); mma_bf16(accg[mt][1], al, b0 + 2);
                mma_bf16(accu[mt][0], ah, b2 + 0); mma_bf16(accu[mt][1], ah, b2 + 2);
                mma_bf16(accu[mt][0], ah, b3 + 0); mma_bf16(accu[mt][1], ah, b3 + 2);
                mma_bf16(accu[mt][0], al, b2 + 0); mma_bf16(accu[mt][1], al, b2 + 2);
            }
        }
        __syncthreads();
    }

    // epilogue: act = silu(g) * u, split to bf16 hi/lo
    const int rw = lane >> 2;
    const int cw = (lane & 3) * 2;
    #pragma unroll
    for (int mt = 0; mt < 4; mt++) {
        #pragma unroll
        for (int half = 0; half < 2; half++) {
            const int slot = m0 + wm * 64 + mt * 16 + rw + half * 8;
            if (slot < cnt) {
                const size_t rowoff = (size_t)(g_base[e] + slot) * HDIM;
                #pragma unroll
                for (int nt = 0; nt < 2; nt++) {
                    float g0 = accg[mt][nt][half * 2 + 0], g1 = accg[mt][nt][half * 2 + 1];
                    float u0 = accu[mt][nt][half * 2 + 0], u1 = accu[mt][nt][half * 2 + 1];
                    float v0 = (g0 / (1.0f + __expf(-g0))) * u0;
                    float v1 = (g1 / (1.0f + __expf(-g1))) * u1;
                    const int col = n0 + wn * 16 + nt * 8 + cw;
                    bf16 h0, l0, h1, l1;
                    split_bf16(v0, h0, l0);
                    split_bf16(v1, h1, l1);
                    __nv_bfloat162 ph; ph.x = h0; ph.y = h1;
                    __nv_bfloat162 pl; pl.x = l0; pl.y = l1;
                    *(__nv_bfloat162*)(g_acth + rowoff + col) = ph;
                    *(__nv_bfloat162*)(g_actl + rowoff + col) = pl;
                }
            }
        }
    }
}

// ===================== phase 2: down GEMM + weighted scatter =====================
// 256 threads, M=128 N=128 (over D) K=32, warps 2m x 4n (warp N=32), 2-stage
__global__ __launch_bounds__(256, 2)
void k_down_mma(float* __restrict__ out) {
    const int e = blockIdx.z;
    const int cnt = g_cnt[e];
    const int m0 = blockIdx.y * 128;
    if (m0 >= cnt) return;
    const int n0 = blockIdx.x * 128;   // over D: 6 tiles

    extern __shared__ char sm[];
    __shared__ int   s_tok[128];
    __shared__ float s_wt[128];
    const int tid = threadIdx.x, lane = tid & 31, wid = tid >> 5;
    const int wm = wid >> 2, wn = wid & 3;
    if (tid < 128) {
        int s = m0 + tid;
        s_tok[tid] = (s < cnt) ? g_tok[e][s] : -1;
        s_wt[tid]  = (s < cnt) ? g_wt[e][s] : 0.0f;
    }
    __syncthreads();
    const uint32_t smb = smem_u32(sm);

    const size_t woff = (size_t)(e * DDIM + n0) * HDIM;
    const bf16* wb0 = g_wdh + woff;
    const bf16* wb1 = g_wdl + woff;
    const size_t abase = (size_t)(g_base[e] + m0) * HDIM;

    auto issue = [&](int stage, int h0) {
        uint32_t sb = smb + stage * STG2;
        #pragma unroll
        for (int i = 0; i < 4; i++) {       // A: acth, actl (128 rows x 32k each)
            int idx = tid + i * 256;
            int tile = idx >> 9, rem = idx & 511, row = rem >> 2, seg = rem & 3;
            const bool ok = (m0 + row) < cnt;
            const bf16* src = (tile ? g_actl : g_acth)
                + abase + (size_t)(ok ? row : 0) * HDIM + h0 + seg * 8;
            cp16(sb + tile * A_TILE + row * PITCH + seg * 16, src, ok ? 16u : 0u);
        }
        #pragma unroll
        for (int i = 0; i < 4; i++) {       // B: wdh, wdl (128 N-rows x 32k each)
            int idx = tid + i * 256;
            int mat = idx >> 9, rem = idx & 511, row = rem >> 2, seg = rem & 3;
            const bf16* src = (mat == 0 ? wb0 : wb1) + (size_t)row * HDIM + h0 + seg * 8;
            cp16(sb + (2 + mat) * A_TILE + row * PITCH + seg * 16, src, 16u);
        }
        CP_COMMIT();
    };

    float acc[4][4][4] = {};

    issue(0, 0);
    const uint32_t aBase = (uint32_t)((wm * 64 + (lane & 15)) * PITCH + ((lane >> 4) * 16));
    const uint32_t bBase = (uint32_t)((wn * 32 + (lane & 7) + ((lane & 16) ? 8 : 0)) * PITCH
                                      + (((lane >> 3) & 1) * 16));

    for (int c = 0; c < NCH2; c++) {
        if (c + 1 < NCH2) { issue((c + 1) & 1, (c + 1) * 32); CP_WAIT_1(); }
        else               { CP_WAIT_0(); }
        __syncthreads();
        const uint32_t sA = smb + (c & 1) * STG2;
        const uint32_t sB = sA + 2 * A_TILE;
        #pragma unroll
        for (int ks = 0; ks < 2; ks++) {
            const uint32_t kc = ks * 32;
            uint32_t bh[2][4], bl[2][4];
            ldsm_x4(bh[0], sB + 0 * A_TILE + bBase + kc);
            ldsm_x4(bh[1], sB + 0 * A_TILE + bBase + 16 * PITCH + kc);
            ldsm_x4(bl[0], sB + 1 * A_TILE + bBase + kc);
            ldsm_x4(bl[1], sB + 1 * A_TILE + bBase + 16 * PITCH + kc);
            #pragma unroll
            for (int mt = 0; mt < 4; mt++) {
                uint32_t ah[4], al[4];
                const uint32_t ao = aBase + mt * 16 * PITCH + kc;
                ldsm_x4(ah, sA + ao);
                ldsm_x4(al, sA + A_TILE + ao);
                #pragma unroll
                for (int ns = 0; ns < 2; ns++) {
                    mma_bf16(acc[mt][ns * 2 + 0], ah, bh[ns] + 0);
                    mma_bf16(acc[mt][ns * 2 + 1], ah, bh[ns] + 2);
                    mma_bf16(acc[mt][ns * 2 + 0], ah, bl[ns] + 0);
                    mma_bf16(acc[mt][ns * 2 + 1], ah, bl[ns] + 2);
                    mma_bf16(acc[mt][ns * 2 + 0], al, bh[ns] + 0);
                    mma_bf16(acc[mt][ns * 2 + 1], al, bh[ns] + 2);
                }
            }
        }
        __syncthreads();
    }

    // epilogue: out[token] += weight * val (atomic)
    const int rw = lane >> 2;
    const int cw = (lane & 3) * 2;
    #pragma unroll
    for (int mt = 0; mt < 4; mt++) {
        #pragma unroll
        for (int half = 0; half < 2; half++) {
            const int lrow = wm * 64 + mt * 16 + rw + half * 8;
            const int slot = m0 + lrow;
            if (slot < cnt) {
                const int t = s_tok[lrow];
                const float w = s_wt[lrow];
                float* dst = out + (size_t)t * DDIM;
                #pragma unroll
                for (int nt = 0; nt < 4; nt++) {
                    const int col = n0 + wn * 32 + nt * 8 + cw;
                    atomicAdd(dst + col,     w * acc[mt][nt][half * 2 + 0]);
                    atomicAdd(dst + col + 1, w * acc[mt][nt][half * 2 + 1]);
                }
            }
        }
    }
}

// ===================== z-loss =====================
__global__ void k_zloss(float* __restrict__ zout) {
    zout[0] = Z_COEFF * g_zsum / (float)T_TOKENS;
}

// ===================== launch =====================
extern "C" void kernel_launch(void* const* d_in, const int* in_sizes, int n_in,
                              void* d_out, int out_size) {
    const float* x           = (const float*)d_in[0];
    const float* gate_w      = (const float*)d_in[1];
    const float* expert_bias = (const float*)d_in[2];
    const float* w_gate      = (const float*)d_in[3];
    const float* w_up        = (const float*)d_in[4];
    const float* w_down      = (const float*)d_in[5];
    float* out = (float*)d_out;

    cudaFuncSetAttribute(k_gu_mma,   cudaFuncAttributeMaxDynamicSharedMemorySize, 2 * STG1);
    cudaFuncSetAttribute(k_down_mma, cudaFuncAttributeMaxDynamicSharedMemorySize, 2 * STG2);

    const int n_main = T_TOKENS * DDIM;

    k_init<<<(out_size / 4 + 255) / 256, 256>>>(out, out_size);
    k_router<<<T_TOKENS, 256>>>(x, gate_w, expert_bias);
    k_offsets<<<1, 32>>>();
    k_split_wgu<<<dim3(HDIM / 32, DDIM / 64, NEXP * 2), 256>>>(w_gate, w_up);
    k_split_wdn<<<dim3(DDIM / 32, HDIM / 64, NEXP), 256>>>(w_down);
    k_gu_mma<<<dim3(HDIM / 64, T_TOKENS / 128, NEXP), 256, 2 * STG1>>>();
    k_down_mma<<<dim3(DDIM / 128, T_TOKENS / 128, NEXP), 256, 2 * STG2>>>(out);
    if (out_size > n_main) k_zloss<<<1, 1>>>(out + n_main);
}

// round 12
// speedup vs baseline: 1.2068x; 1.0150x over previous
#include <cuda_runtime.h>
#include <cuda_bf16.h>
#include <stdint.h>
#include <math.h>

#define T_TOKENS 4096
#define DDIM 768
#define HDIM 2688
#define NEXP 8
#define Z_COEFF 1e-5f

typedef __nv_bfloat16 bf16;

// ===================== helpers =====================
__device__ __forceinline__ uint32_t smem_u32(const void* p) {
    uint32_t a;
    asm("{ .reg .u64 t; cvta.to.shared.u64 t, %1; cvt.u32.u64 %0, t; }" : "=r"(a) : "l"(p));
    return a;
}
__device__ __forceinline__ void ldsm_x4(uint32_t* r, uint32_t a) {
    asm volatile("ldmatrix.sync.aligned.m8n8.x4.shared.b16 {%0,%1,%2,%3}, [%4];"
        : "=r"(r[0]), "=r"(r[1]), "=r"(r[2]), "=r"(r[3]) : "r"(a));
}
__device__ __forceinline__ void mma_bf16(float* c, const uint32_t* a, const uint32_t* b) {
    asm volatile("mma.sync.aligned.m16n8k16.row.col.f32.bf16.bf16.f32 "
        "{%0,%1,%2,%3}, {%4,%5,%6,%7}, {%8,%9}, {%0,%1,%2,%3};"
        : "+f"(c[0]), "+f"(c[1]), "+f"(c[2]), "+f"(c[3])
        : "r"(a[0]), "r"(a[1]), "r"(a[2]), "r"(a[3]), "r"(b[0]), "r"(b[1]));
}
__device__ __forceinline__ void cp16(uint32_t dst, const void* src, uint32_t sz) {
    asm volatile("cp.async.ca.shared.global [%0], [%1], 16, %2;"
        :: "r"(dst), "l"(src), "r"(sz) : "memory");
}
#define CP_COMMIT() asm volatile("cp.async.commit_group;" ::: "memory")
#define CP_WAIT_1() asm volatile("cp.async.wait_group 1;" ::: "memory")
#define CP_WAIT_0() asm volatile("cp.async.wait_group 0;" ::: "memory")

// ===================== device scratch =====================
__device__ int   g_cnt[NEXP];
__device__ int   g_base[NEXP];
__device__ int   g_tok[NEXP][T_TOKENS];
__device__ float g_wt[NEXP][T_TOKENS];
__device__ float g_zsum;
__device__ bf16  g_xh[(size_t)T_TOKENS * DDIM];
__device__ bf16  g_xl[(size_t)T_TOKENS * DDIM];
// transposed split weights: [E][H][D] for gate/up, [E][D][H] for down
__device__ bf16  g_wgh[(size_t)NEXP * HDIM * DDIM];
__device__ bf16  g_wgl[(size_t)NEXP * HDIM * DDIM];
__device__ bf16  g_wuh[(size_t)NEXP * HDIM * DDIM];
__device__ bf16  g_wul[(size_t)NEXP * HDIM * DDIM];
__device__ bf16  g_wdh[(size_t)NEXP * DDIM * HDIM];
__device__ bf16  g_wdl[(size_t)NEXP * DDIM * HDIM];
// split activations, compact rows (g_base[e] + slot)
__device__ bf16  g_acth[(size_t)2 * T_TOKENS * HDIM];
__device__ bf16  g_actl[(size_t)2 * T_TOKENS * HDIM];

// ===================== init (vectorized) =====================
__global__ void k_init(float* __restrict__ out, int n) {
    const int n4 = n >> 2;
    int i = blockIdx.x * blockDim.x + threadIdx.x;
    if (i < n4) ((float4*)out)[i] = make_float4(0.f, 0.f, 0.f, 0.f);
    if (blockIdx.x == 0) {
        if (threadIdx.x < NEXP) g_cnt[threadIdx.x] = 0;
        if (threadIdx.x == 0) {
            g_zsum = 0.0f;
            for (int r = n4 << 2; r < n; r++) out[r] = 0.0f;
        }
    }
}

// ===================== precision split helper =====================
__device__ __forceinline__ void split_bf16(float v, bf16& h, bf16& l) {
    h = __float2bfloat16(v);
    l = __float2bfloat16(v - __bfloat162float(h));
}

// ===================== router (+ fused x hi/lo split) =====================
__global__ void k_router(const float* __restrict__ x,
                         const float* __restrict__ gw,
                         const float* __restrict__ bias) {
    const int t = blockIdx.x;
    __shared__ float s_logits[NEXP];
    const int tid = threadIdx.x;
    const int warp = tid >> 5;
    const int lane = tid & 31;
    const float* xr = x + (size_t)t * DDIM;
    const float* w = gw + (size_t)warp * DDIM;
    float s = 0.0f;
    for (int d = lane; d < DDIM; d += 32) s = fmaf(xr[d], w[d], s);
    #pragma unroll
    for (int o = 16; o; o >>= 1) s += __shfl_xor_sync(0xffffffffu, s, o);
    if (lane == 0) s_logits[warp] = s;

    // fused x split: this block owns token t's row (L1-hot)
    for (int i = tid; i < DDIM; i += 256) {
        bf16 h, l; split_bf16(xr[i], h, l);
        g_xh[(size_t)t * DDIM + i] = h;
        g_xl[(size_t)t * DDIM + i] = l;
    }

    __syncthreads();
    if (tid == 0) {
        float l[NEXP];
        #pragma unroll
        for (int e = 0; e < NEXP; e++) l[e] = s_logits[e];
        int i0 = 0, i1 = -1;
        float b0 = -1e30f, b1 = -1e30f;
        #pragma unroll
        for (int e = 0; e < NEXP; e++) {
            float v = l[e] + bias[e];
            if (v > b0) { b1 = b0; i1 = i0; b0 = v; i0 = e; }
            else if (v > b1) { b1 = v; i1 = e; }
        }
        float l0 = l[i0], l1 = l[i1];
        float m = fmaxf(l0, l1);
        float e0 = expf(l0 - m), e1 = expf(l1 - m);
        float inv = 1.0f / (e0 + e1);
        float mx = l[0];
        #pragma unroll
        for (int e = 1; e < NEXP; e++) mx = fmaxf(mx, l[e]);
        float se = 0.0f;
        #pragma unroll
        for (int e = 0; e < NEXP; e++) se += expf(l[e] - mx);
        float lse = mx + logf(se);
        atomicAdd(&g_zsum, lse * lse);
        int p0 = atomicAdd(&g_cnt[i0], 1);
        g_tok[i0][p0] = t; g_wt[i0][p0] = e0 * inv;
        int p1 = atomicAdd(&g_cnt[i1], 1);
        g_tok[i1][p1] = t; g_wt[i1][p1] = e1 * inv;
    }
}

__global__ void k_offsets() {
    if (threadIdx.x == 0) {
        int s = 0;
        for (int e = 0; e < NEXP; e++) { g_base[e] = s; s += g_cnt[e]; }
    }
}

// transpose+split w_gate / w_up : [E][D][H] -> [E][H][D], vectorized 16B stores
__global__ __launch_bounds__(256) void k_split_wgu(const float* __restrict__ w_gate,
                                                   const float* __restrict__ w_up) {
    __shared__ float t[64][33];
    const int z = blockIdx.z;
    const int e = z >> 1;
    const bool up = z & 1;
    const float* src = (up ? w_up : w_gate) + (size_t)e * DDIM * HDIM;
    bf16* oh = (up ? g_wuh : g_wgh) + (size_t)e * HDIM * DDIM;
    bf16* ol = (up ? g_wul : g_wgl) + (size_t)e * HDIM * DDIM;
    const int h0 = blockIdx.x * 32, d0 = blockIdx.y * 64;
    const int c = threadIdx.x & 31, r0 = threadIdx.x >> 5;
    #pragma unroll
    for (int i = 0; i < 64; i += 8)
        t[r0 + i][c] = src[(size_t)(d0 + r0 + i) * HDIM + h0 + c];
    __syncthreads();
    const int h = threadIdx.x >> 3, dg = threadIdx.x & 7;
    union { bf16 b[8]; uint4 u; } H, L;
    #pragma unroll
    for (int j = 0; j < 8; j++) split_bf16(t[dg * 8 + j][h], H.b[j], L.b[j]);
    const size_t o = (size_t)(h0 + h) * DDIM + d0 + dg * 8;
    *(uint4*)(oh + o) = H.u;
    *(uint4*)(ol + o) = L.u;
}

// transpose+split w_down : [E][H][D] -> [E][D][H], vectorized 16B stores
__global__ __launch_bounds__(256) void k_split_wdn(const float* __restrict__ w_down) {
    __shared__ float t[64][33];
    const int e = blockIdx.z;
    const float* src = w_down + (size_t)e * HDIM * DDIM;
    bf16* oh = g_wdh + (size_t)e * DDIM * HDIM;
    bf16* ol = g_wdl + (size_t)e * DDIM * HDIM;
    const int d0 = blockIdx.x * 32, h0 = blockIdx.y * 64;
    const int c = threadIdx.x & 31, r0 = threadIdx.x >> 5;
    #pragma unroll
    for (int i = 0; i < 64; i += 8)
        t[r0 + i][c] = src[(size_t)(h0 + r0 + i) * DDIM + d0 + c];
    __syncthreads();
    const int d = threadIdx.x >> 3, hg = threadIdx.x & 7;
    union { bf16 b[8]; uint4 u; } H, L;
    #pragma unroll
    for (int j = 0; j < 8; j++) split_bf16(t[hg * 8 + j][d], H.b[j], L.b[j]);
    const size_t o = (size_t)(d0 + d) * HDIM + h0 + hg * 8;
    *(uint4*)(oh + o) = H.u;
    *(uint4*)(ol + o) = L.u;
}

// ===================== GEMM tiling constants (R9-proven) =====================
#define PITCH 80                      // 64B data + 16B pad; conflict-free ldmatrix
#define A_TILE (128 * PITCH)          // 10240 B (128 rows x 32 k)
#define B_TILE (64 * PITCH)           // 5120 B
#define STG1 (2 * A_TILE + 4 * B_TILE)   // 40960
#define STG2 (4 * A_TILE)                // 40960 (A hi/lo + B 128-row hi/lo)
#define NCH1 (DDIM / 32)              // 24
#define KSPLIT2 2
#define KHALF (HDIM / KSPLIT2)        // 1344
#define NCH2 (KHALF / 32)             // 42

// ===================== phase 1: gate+up GEMM (R9-proven config) =====================
// 256 threads, M=128 N=64 K=32, warps 2m x 4n, 2-stage cp.async
__global__ __launch_bounds__(256, 2)
void k_gu_mma() {
    const int e = blockIdx.z;
    const int cnt = g_cnt[e];
    const int m0 = blockIdx.y * 128;
    if (m0 >= cnt) return;
    const int n0 = blockIdx.x * 64;

    extern __shared__ char sm[];
    __shared__ int s_tok[128];
    const int tid = threadIdx.x, lane = tid & 31, wid = tid >> 5;
    const int wm = wid >> 2, wn = wid & 3;
    if (tid < 128) { int s = m0 + tid; s_tok[tid] = (s < cnt) ? g_tok[e][s] : -1; }
    __syncthreads();
    const uint32_t smb = smem_u32(sm);

    const size_t woff = (size_t)(e * HDIM + n0) * DDIM;
    const bf16* wb0 = g_wgh + woff;
    const bf16* wb1 = g_wgl + woff;
    const bf16* wb2 = g_wuh + woff;
    const bf16* wb3 = g_wul + woff;

    auto issue = [&](int stage, int d0) {
        uint32_t sb = smb + stage * STG1;
        #pragma unroll
        for (int i = 0; i < 4; i++) {
            int idx = tid + i * 256;
            int tile = idx >> 9, rem = idx & 511, row = rem >> 2, seg = rem & 3;
            int tok = s_tok[row];
            const bf16* src = (tile ? g_xl : g_xh)
                + (size_t)(tok < 0 ? 0 : tok) * DDIM + d0 + seg * 8;
            cp16(sb + tile * A_TILE + row * PITCH + seg * 16, src, tok >= 0 ? 16u : 0u);
        }
        #pragma unroll
        for (int i = 0; i < 4; i++) {
            int idx = tid + i * 256;
            int mat = idx >> 8, rem = idx & 255, row = rem >> 2, seg = rem & 3;
            const bf16* src = (mat == 0 ? wb0 : mat == 1 ? wb1 : mat == 2 ? wb2 : wb3)
                + (size_t)row * DDIM + d0 + seg * 8;
            cp16(sb + 2 * A_TILE + mat * B_TILE + row * PITCH + seg * 16, src, 16u);
        }
        CP_COMMIT();
    };

    float accg[4][2][4] = {};
    float accu[4][2][4] = {};

    issue(0, 0);
    const uint32_t aBase = (uint32_t)((wm * 64 + (lane & 15)) * PITCH + ((lane >> 4) * 16));
    const uint32_t bBase = (uint32_t)((wn * 16 + (lane & 7) + ((lane & 16) ? 8 : 0)) * PITCH
                                      + (((lane >> 3) & 1) * 16));

    for (int c = 0; c < NCH1; c++) {
        if (c + 1 < NCH1) { issue((c + 1) & 1, (c + 1) * 32); CP_WAIT_1(); }
        else               { CP_WAIT_0(); }
        __syncthreads();
        const uint32_t sA = smb + (c & 1) * STG1;
        const uint32_t sB = sA + 2 * A_TILE;
        #pragma unroll
        for (int ks = 0; ks < 2; ks++) {
            const uint32_t kc = ks * 32;
            uint32_t b0[4], b1[4], b2[4], b3[4];
            ldsm_x4(b0, sB + 0 * B_TILE + bBase + kc);
            ldsm_x4(b1, sB + 1 * B_TILE + bBase + kc);
            ldsm_x4(b2, sB + 2 * B_TILE + bBase + kc);
            ldsm_x4(b3, sB + 3 * B_TILE + bBase + kc);
            #pragma unroll
            for (int mt = 0; mt < 4; mt++) {
                uint32_t ah[4], al[4];
                const uint32_t ao = aBase + mt * 16 * PITCH + kc;
                ldsm_x4(ah, sA + ao);
                ldsm_x4(al, sA + A_TILE + ao);
                mma_bf16(accg[mt][0], ah, b0 + 0); mma_bf16(accg[mt][1], ah, b0 + 2);
                mma_bf16(accg[mt][0], ah, b1 + 0); mma_bf16(accg[mt][1], ah, b1 + 2);
                mma_bf16(accg[mt][0], al, b0 + 0); mma_bf16(accg[mt][1], al, b0 + 2);
                mma_bf16(accu[mt][0], ah, b2 + 0); mma_bf16(accu[mt][1], ah, b2 + 2);
                mma_bf16(accu[mt][0], ah, b3 + 0); mma_bf16(accu[mt][1], ah, b3 + 2);
                mma_bf16(accu[mt][0], al, b2 + 0); mma_bf16(accu[mt][1], al, b2 + 2);
            }
        }
        __syncthreads();
    }

    // epilogue: act = silu(g) * u, split to bf16 hi/lo
    const int rw = lane >> 2;
    const int cw = (lane & 3) * 2;
    #pragma unroll
    for (int mt = 0; mt < 4; mt++) {
        #pragma unroll
        for (int half = 0; half < 2; half++) {
            const int slot = m0 + wm * 64 + mt * 16 + rw + half * 8;
            if (slot < cnt) {
                const size_t rowoff = (size_t)(g_base[e] + slot) * HDIM;
                #pragma unroll
                for (int nt = 0; nt < 2; nt++) {
                    float g0 = accg[mt][nt][half * 2 + 0], g1 = accg[mt][nt][half * 2 + 1];
                    float u0 = accu[mt][nt][half * 2 + 0], u1 = accu[mt][nt][half * 2 + 1];
                    float v0 = (g0 / (1.0f + __expf(-g0))) * u0;
                    float v1 = (g1 / (1.0f + __expf(-g1))) * u1;
                    const int col = n0 + wn * 16 + nt * 8 + cw;
                    bf16 h0, l0, h1, l1;
                    split_bf16(v0, h0, l0);
                    split_bf16(v1, h1, l1);
                    __nv_bfloat162 ph; ph.x = h0; ph.y = h1;
                    __nv_bfloat162 pl; pl.x = l0; pl.y = l1;
                    *(__nv_bfloat162*)(g_acth + rowoff + col) = ph;
                    *(__nv_bfloat162*)(g_actl + rowoff + col) = pl;
                }
            }
        }
    }
}

// ===================== phase 2: down GEMM + weighted scatter (split-K=2) =====================
// 256 threads, M=128 N=128 (over D) Kslice=1344, warps 2m x 4n (warp N=32), 2-stage
__global__ __launch_bounds__(256, 2)
void k_down_mma(float* __restrict__ out) {
    const int z = blockIdx.z;
    const int e = z >> 1;
    const int k0 = (z & 1) * KHALF;
    const int cnt = g_cnt[e];
    const int m0 = blockIdx.y * 128;
    if (m0 >= cnt) return;
    const int n0 = blockIdx.x * 128;   // over D: 6 tiles

    extern __shared__ char sm[];
    __shared__ int   s_tok[128];
    __shared__ float s_wt[128];
    const int tid = threadIdx.x, lane = tid & 31, wid = tid >> 5;
    const int wm = wid >> 2, wn = wid & 3;
    if (tid < 128) {
        int s = m0 + tid;
        s_tok[tid] = (s < cnt) ? g_tok[e][s] : -1;
        s_wt[tid]  = (s < cnt) ? g_wt[e][s] : 0.0f;
    }
    __syncthreads();
    const uint32_t smb = smem_u32(sm);

    const size_t woff = (size_t)(e * DDIM + n0) * HDIM;
    const bf16* wb0 = g_wdh + woff;
    const bf16* wb1 = g_wdl + woff;
    const size_t abase = (size_t)(g_base[e] + m0) * HDIM;

    auto issue = [&](int stage, int h0) {
        uint32_t sb = smb + stage * STG2;
        #pragma unroll
        for (int i = 0; i < 4; i++) {       // A: acth, actl (128 rows x 32k each)
            int idx = tid + i * 256;
            int tile = idx >> 9, rem = idx & 511, row = rem >> 2, seg = rem & 3;
            const bool ok = (m0 + row) < cnt;
            const bf16* src = (tile ? g_actl : g_acth)
                + abase + (size_t)(ok ? row : 0) * HDIM + h0 + seg * 8;
            cp16(sb + tile * A_TILE + row * PITCH + seg * 16, src, ok ? 16u : 0u);
        }
        #pragma unroll
        for (int i = 0; i < 4; i++) {       // B: wdh, wdl (128 N-rows x 32k each)
            int idx = tid + i * 256;
            int mat = idx >> 9, rem = idx & 511, row = rem >> 2, seg = rem & 3;
            const bf16* src = (mat == 0 ? wb0 : wb1) + (size_t)row * HDIM + h0 + seg * 8;
            cp16(sb + (2 + mat) * A_TILE + row * PITCH + seg * 16, src, 16u);
        }
        CP_COMMIT();
    };

    float acc[4][4][4] = {};

    issue(0, k0);
    const uint32_t aBase = (uint32_t)((wm * 64 + (lane & 15)) * PITCH + ((lane >> 4) * 16));
    const uint32_t bBase = (uint32_t)((wn * 32 + (lane & 7) + ((lane & 16) ? 8 : 0)) * PITCH
                                      + (((lane >> 3) & 1) * 16));

    for (int c = 0; c < NCH2; c++) {
        if (c + 1 < NCH2) { issue((c + 1) & 1, k0 + (c + 1) * 32); CP_WAIT_1(); }
        else               { CP_WAIT_0(); }
        __syncthreads();
        const uint32_t sA = smb + (c & 1) * STG2;
        const uint32_t sB = sA + 2 * A_TILE;
        #pragma unroll
        for (int ks = 0; ks < 2; ks++) {
            const uint32_t kc = ks * 32;
            uint32_t bh[2][4], bl[2][4];
            ldsm_x4(bh[0], sB + 0 * A_TILE + bBase + kc);
            ldsm_x4(bh[1], sB + 0 * A_TILE + bBase + 16 * PITCH + kc);
            ldsm_x4(bl[0], sB + 1 * A_TILE + bBase + kc);
            ldsm_x4(bl[1], sB + 1 * A_TILE + bBase + 16 * PITCH + kc);
            #pragma unroll
            for (int mt = 0; mt < 4; mt++) {
                uint32_t ah[4], al[4];
                const uint32_t ao = aBase + mt * 16 * PITCH + kc;
                ldsm_x4(ah, sA + ao);
                ldsm_x4(al, sA + A_TILE + ao);
                #pragma unroll
                for (int ns = 0; ns < 2; ns++) {
                    mma_bf16(acc[mt][ns * 2 + 0], ah, bh[ns] + 0);
                    mma_bf16(acc[mt][ns * 2 + 1], ah, bh[ns] + 2);
                    mma_bf16(acc[mt][ns * 2 + 0], ah, bl[ns] + 0);
                    mma_bf16(acc[mt][ns * 2 + 1], ah, bl[ns] + 2);
                    mma_bf16(acc[mt][ns * 2 + 0], al, bh[ns] + 0);
                    mma_bf16(acc[mt][ns * 2 + 1], al, bh[ns] + 2);
                }
            }
        }
        __syncthreads();
    }

    // epilogue: out[token] += weight * val (atomic; split-K partials accumulate)
    const int rw = lane >> 2;
    const int cw = (lane & 3) * 2;
    #pragma unroll
    for (int mt = 0; mt < 4; mt++) {
        #pragma unroll
        for (int half = 0; half < 2; half++) {
            const int lrow = wm * 64 + mt * 16 + rw + half * 8;
            const int slot = m0 + lrow;
            if (slot < cnt) {
                const int t = s_tok[lrow];
                const float w = s_wt[lrow];
                float* dst = out + (size_t)t * DDIM;
                #pragma unroll
                for (int nt = 0; nt < 4; nt++) {
                    const int col = n0 + wn * 32 + nt * 8 + cw;
                    atomicAdd(dst + col,     w * acc[mt][nt][half * 2 + 0]);
                    atomicAdd(dst + col + 1, w * acc[mt][nt][half * 2 + 1]);
                }
            }
        }
    }
}

// ===================== z-loss =====================
__global__ void k_zloss(float* __restrict__ zout) {
    zout[0] = Z_COEFF * g_zsum / (float)T_TOKENS;
}

// ===================== launch =====================
extern "C" void kernel_launch(void* const* d_in, const int* in_sizes, int n_in,
                              void* d_out, int out_size) {
    const float* x           = (const float*)d_in[0];
    const float* gate_w      = (const float*)d_in[1];
    const float* expert_bias = (const float*)d_in[2];
    const float* w_gate      = (const float*)d_in[3];
    const float* w_up        = (const float*)d_in[4];
    const float* w_down      = (const float*)d_in[5];
    float* out = (float*)d_out;

    cudaFuncSetAttribute(k_gu_mma,   cudaFuncAttributeMaxDynamicSharedMemorySize, 2 * STG1);
    cudaFuncSetAttribute(k_down_mma, cudaFuncAttributeMaxDynamicSharedMemorySize, 2 * STG2);

    const int n_main = T_TOKENS * DDIM;

    k_init<<<(out_size / 4 + 255) / 256, 256>>>(out, out_size);
    k_router<<<T_TOKENS, 256>>>(x, gate_w, expert_bias);
    k_offsets<<<1, 32>>>();
    k_split_wgu<<<dim3(HDIM / 32, DDIM / 64, NEXP * 2), 256>>>(w_gate, w_up);
    k_split_wdn<<<dim3(DDIM / 32, HDIM / 64, NEXP), 256>>>(w_down);
    k_gu_mma<<<dim3(HDIM / 64, T_TOKENS / 128, NEXP), 256, 2 * STG1>>>();
    k_down_mma<<<dim3(DDIM / 128, T_TOKENS / 128, NEXP * KSPLIT2), 256, 2 * STG2>>>(out);
    if (out_size > n_main) k_zloss<<<1, 1>>>(out + n_main);
}